// round 2
// baseline (speedup 1.0000x reference)
#include <cuda_runtime.h>
#include <math.h>

// ---------------- problem constants ----------------
#define BATCH 2
#define NCLS 24
#define NHEADS 8
#define CIN0 1024
#define CPROJ 128
// decoder dims (input side of each convT)
// L1: 1024->512  @ 4x6x8
// L2: 512->256   @ 8x12x16
// L3: 256->128   @ 16x24x32
// L4: 128->32    @ 32x48x64
// L5: 32->1      @ 64x96x128 (sigmoid epilogue -> d_out)

// ---------------- scratch (static device memory; no allocs) ----------------
__device__ float g_wproj[(size_t)BATCH * NHEADS * CPROJ * CIN0];          // 2*8*128*1024
__device__ float g_t0[(size_t)BATCH * 1024 * 4 * 6 * 8];
__device__ float g_t1[(size_t)BATCH * 512 * 8 * 12 * 16];
__device__ float g_t2[(size_t)BATCH * 256 * 16 * 24 * 32];
__device__ float g_t3[(size_t)BATCH * 128 * 32 * 48 * 64];
__device__ float g_t4[(size_t)BATCH * 32 * 64 * 96 * 128];
__device__ float g_part[1024 * 16 * 2];
__device__ float g_scale[1024];
__device__ float g_shift[1024];

// ---------------- hypernet: w[b,h,k] = sum_q y[b,q] * tables[h,q,k] ----------------
__global__ void hyper_kernel(const float* __restrict__ y,
                             const float* __restrict__ tables,
                             float* __restrict__ wout) {
    const int K = CPROJ * CIN0;
    int gid = blockIdx.x * blockDim.x + threadIdx.x;
    if (gid >= NHEADS * K) return;
    int h = gid / K;
    int k = gid - h * K;
    const float* t = tables + (size_t)h * NCLS * K + k;
    float a0 = 0.f, a1 = 0.f;
#pragma unroll
    for (int q = 0; q < NCLS; q++) {
        float tv = t[(size_t)q * K];
        a0 += y[q] * tv;
        a1 += y[NCLS + q] * tv;
    }
    wout[(size_t)0 * NHEADS * K + gid] = a0;
    wout[(size_t)1 * NHEADS * K + gid] = a1;
}

// ---------------- projection: t0[b,ho,s] = sum_c w[b,ho,c] * x[b,c,s] ----------------
__global__ void proj_kernel(const float* __restrict__ x,
                            const float* __restrict__ w,
                            float* __restrict__ out) {
    const int S = 4 * 6 * 8;  // 192
    int gid = blockIdx.x * blockDim.x + threadIdx.x;
    if (gid >= BATCH * 1024 * S) return;
    int s = gid % S;
    int ho = (gid / S) % 1024;
    int b = gid / (S * 1024);
    const float* wp = w + ((size_t)b * 1024 + ho) * 1024;
    const float* xp = x + (size_t)b * 1024 * S + s;
    float acc = 0.f;
#pragma unroll 4
    for (int c = 0; c < 1024; c++) {
        acc = fmaf(wp[c], xp[(size_t)c * S], acc);
    }
    out[gid] = acc;
}

// ---------------- BatchNorm (training mode, biased var) ----------------
#define BN_NB 16
__global__ void bn_partial(const float* __restrict__ x, int C, int S,
                           float* __restrict__ part) {
    int c = blockIdx.x;
    int nb = blockIdx.y;
    int n = BATCH * S;
    float s1 = 0.f, s2 = 0.f;
    for (int e = nb * blockDim.x + threadIdx.x; e < n; e += BN_NB * blockDim.x) {
        int bb = e / S;
        int sp = e - bb * S;
        float v = x[((size_t)bb * C + c) * S + sp];
        s1 += v;
        s2 += v * v;
    }
    __shared__ float r1[256];
    __shared__ float r2[256];
    r1[threadIdx.x] = s1;
    r2[threadIdx.x] = s2;
    __syncthreads();
    for (int st = 128; st > 0; st >>= 1) {
        if (threadIdx.x < st) {
            r1[threadIdx.x] += r1[threadIdx.x + st];
            r2[threadIdx.x] += r2[threadIdx.x + st];
        }
        __syncthreads();
    }
    if (threadIdx.x == 0) {
        part[(c * BN_NB + nb) * 2 + 0] = r1[0];
        part[(c * BN_NB + nb) * 2 + 1] = r2[0];
    }
}

__global__ void bn_finalize(const float* __restrict__ part, int C, float n,
                            const float* __restrict__ g, const float* __restrict__ be,
                            float* __restrict__ scale, float* __restrict__ shift) {
    int c = blockIdx.x * blockDim.x + threadIdx.x;
    if (c >= C) return;
    float s1 = 0.f, s2 = 0.f;
    for (int i = 0; i < BN_NB; i++) {
        s1 += part[(c * BN_NB + i) * 2 + 0];
        s2 += part[(c * BN_NB + i) * 2 + 1];
    }
    float mean = s1 / n;
    float var = s2 / n - mean * mean;
    var = fmaxf(var, 0.f);
    float sc = g[c] * rsqrtf(var + 1e-5f);
    scale[c] = sc;
    shift[c] = be[c] - mean * sc;
}

__global__ void bn_apply_relu(float* __restrict__ x, int C, int S,
                              const float* __restrict__ scale,
                              const float* __restrict__ shift) {
    size_t gid = (size_t)blockIdx.x * blockDim.x + threadIdx.x;
    size_t total = (size_t)BATCH * C * S;
    if (gid >= total) return;
    int c = (int)((gid / S) % C);
    float v = fmaf(x[gid], scale[c], shift[c]);
    x[gid] = v > 0.f ? v : 0.f;
}

// ---------------- ConvTranspose3d k=4 s=2 p=1 ----------------
// out[o, 2m+p] gathers from inputs m + DD[p][s] with tap KK[p][s] per dim:
//   p=0: (d=0,k=1),(d=-1,k=3) ; p=1: (d=+1,k=0),(d=0,k=2)
// Thread owns input cells: 1 z-cell, 2 y-cells, 2 x-cells -> 32 outputs.
// Block: fixed (b, o), 128 threads = 4z x 4y x 8x -> tile 4 x 8 x 16 input cells.
// Weights for (chunk of c, o) staged in smem.
template <bool SIG>
__global__ __launch_bounds__(128, 3) void convt_kernel(
    const float* __restrict__ in, const float* __restrict__ wt,
    const float* __restrict__ bias, float* __restrict__ out,
    int Cin, int Cout, int Dz, int Hy, int Wx, int CC, int ntx, int nty) {
    extern __shared__ float ws[];
    const int tid = threadIdx.x;
    const int o = blockIdx.y;
    const int b = blockIdx.z;
    int tile = blockIdx.x;
    int tix = tile % ntx;
    int t2 = tile / ntx;
    int tiy = t2 % nty;
    int tiz = t2 / nty;

    const int txi = tid & 7;
    const int tyi = (tid >> 3) & 3;
    const int tzi = tid >> 5;
    const int mz = tiz * 4 + tzi;
    const int my0 = tiy * 8 + 2 * tyi;
    const int mx0 = tix * 16 + 2 * txi;

    const int S = Dz * Hy * Wx;

    int zoff[3]; bool zv[3];
#pragma unroll
    for (int j = 0; j < 3; j++) {
        int zi = mz - 1 + j;
        zv[j] = (zi >= 0 && zi < Dz);
        zoff[j] = zv[j] ? zi * Hy * Wx : 0;
    }
    int yoff[4]; bool yv[4];
#pragma unroll
    for (int j = 0; j < 4; j++) {
        int yi = my0 - 1 + j;
        yv[j] = (yi >= 0 && yi < Hy);
        yoff[j] = yv[j] ? yi * Wx : 0;
    }
    int xoff[4]; bool xv[4];
#pragma unroll
    for (int j = 0; j < 4; j++) {
        int xi = mx0 - 1 + j;
        xv[j] = (xi >= 0 && xi < Wx);
        xoff[j] = xv[j] ? xi : 0;
    }

    float acc[2][2][8];
#pragma unroll
    for (int cy = 0; cy < 2; cy++)
#pragma unroll
        for (int cx = 0; cx < 2; cx++)
#pragma unroll
            for (int p = 0; p < 8; p++) acc[cy][cx][p] = 0.f;

    const int DD[2][2] = {{0, -1}, {1, 0}};
    const int KK[2][2] = {{1, 3}, {0, 2}};

    const float* inb = in + (size_t)b * Cin * S;

    for (int c0 = 0; c0 < Cin; c0 += CC) {
        __syncthreads();
        for (int i = tid; i < CC * 64; i += 128) {
            int cl = i >> 6;
            int kidx = i & 63;
            ws[i] = wt[(((size_t)(c0 + cl)) * Cout + o) * 64 + kidx];
        }
        __syncthreads();

        for (int cl = 0; cl < CC; cl++) {
            const float* pc = inb + (size_t)(c0 + cl) * S;
            float v[3][4][4];
#pragma unroll
            for (int jz = 0; jz < 3; jz++)
#pragma unroll
                for (int jy = 0; jy < 4; jy++)
#pragma unroll
                    for (int jx = 0; jx < 4; jx++) {
                        bool m = zv[jz] && yv[jy] && xv[jx];
                        v[jz][jy][jx] = m ? __ldg(pc + zoff[jz] + yoff[jy] + xoff[jx]) : 0.f;
                    }
            const float* wc = ws + cl * 64;
#pragma unroll
            for (int pz = 0; pz < 2; pz++)
#pragma unroll
                for (int sz = 0; sz < 2; sz++) {
                    const int jz = 1 + DD[pz][sz];
                    const int kz = KK[pz][sz];
#pragma unroll
                    for (int py = 0; py < 2; py++)
#pragma unroll
                        for (int sy = 0; sy < 2; sy++) {
                            const int jy0 = 1 + DD[py][sy];
                            const int ky = KK[py][sy];
#pragma unroll
                            for (int px = 0; px < 2; px++)
#pragma unroll
                                for (int sx = 0; sx < 2; sx++) {
                                    const int jx0 = 1 + DD[px][sx];
                                    const int kx = KK[px][sx];
                                    const float wv = wc[kz * 16 + ky * 4 + kx];
                                    const int p = pz * 4 + py * 2 + px;
#pragma unroll
                                    for (int cy = 0; cy < 2; cy++)
#pragma unroll
                                        for (int cx = 0; cx < 2; cx++)
                                            acc[cy][cx][p] = fmaf(
                                                v[jz][cy + jy0][cx + jx0], wv,
                                                acc[cy][cx][p]);
                                }
                        }
                }
        }
    }

    // epilogue
    if (mz >= Dz) return;
    const float bv = bias[o];
    const int Ho = 2 * Hy, Wo = 2 * Wx;
    float* ob = out + ((size_t)b * Cout + o) * (size_t)(2 * Dz) * Ho * Wo;
#pragma unroll
    for (int cy = 0; cy < 2; cy++) {
        int my = my0 + cy;
        if (my >= Hy) continue;
#pragma unroll
        for (int cx = 0; cx < 2; cx++) {
            int mx = mx0 + cx;
            if (mx >= Wx) continue;
#pragma unroll
            for (int pz = 0; pz < 2; pz++)
#pragma unroll
                for (int py = 0; py < 2; py++)
#pragma unroll
                    for (int px = 0; px < 2; px++) {
                        float r = acc[cy][cx][pz * 4 + py * 2 + px] + bv;
                        if (SIG) r = 1.f / (1.f + expf(-r));
                        ob[(size_t)(2 * mz + pz) * Ho * Wo +
                           (size_t)(2 * my + py) * Wo + (2 * mx + px)] = r;
                    }
        }
    }
}

// ---------------- host-side helpers ----------------
static void run_bn(float* t, int C, int S, const float* g, const float* be,
                   float* part, float* scale, float* shift) {
    dim3 gp(C, BN_NB);
    bn_partial<<<gp, 256>>>(t, C, S, part);
    bn_finalize<<<(C + 127) / 128, 128>>>(part, C, (float)(BATCH * S), g, be, scale, shift);
    size_t total = (size_t)BATCH * C * S;
    bn_apply_relu<<<(unsigned)((total + 255) / 256), 256>>>(t, C, S, scale, shift);
}

template <bool SIG>
static void run_convt(const float* in, const float* wt, const float* bias,
                      float* out, int Cin, int Cout, int Dz, int Hy, int Wx) {
    int ntx = (Wx + 15) / 16;
    int nty = (Hy + 7) / 8;
    int ntz = (Dz + 3) / 4;
    int CC = Cin >= 128 ? 128 : Cin;
    dim3 grid(ntx * nty * ntz, Cout, BATCH);
    size_t smem = (size_t)CC * 64 * sizeof(float);
    convt_kernel<SIG><<<grid, 128, smem>>>(in, wt, bias, out, Cin, Cout, Dz, Hy,
                                           Wx, CC, ntx, nty);
}

extern "C" void kernel_launch(void* const* d_in, const int* in_sizes, int n_in,
                              void* d_out, int out_size) {
    const float* x_in = (const float*)d_in[0];
    const float* y_in = (const float*)d_in[1];
    const float* tables = (const float*)d_in[2];
    const float* g0 = (const float*)d_in[3];
    const float* be0 = (const float*)d_in[4];
    const float* g1 = (const float*)d_in[5];
    const float* be1 = (const float*)d_in[6];
    const float* g2 = (const float*)d_in[7];
    const float* be2 = (const float*)d_in[8];
    const float* g3 = (const float*)d_in[9];
    const float* be3 = (const float*)d_in[10];
    const float* g4 = (const float*)d_in[11];
    const float* be4 = (const float*)d_in[12];
    const float* w1 = (const float*)d_in[13];
    const float* b1 = (const float*)d_in[14];
    const float* w2 = (const float*)d_in[15];
    const float* b2 = (const float*)d_in[16];
    const float* w3 = (const float*)d_in[17];
    const float* b3 = (const float*)d_in[18];
    const float* w4 = (const float*)d_in[19];
    const float* b4 = (const float*)d_in[20];
    const float* w5 = (const float*)d_in[21];
    const float* b5 = (const float*)d_in[22];

    float *wproj, *t0, *t1, *t2, *t3, *t4, *part, *scale, *shift;
    cudaGetSymbolAddress((void**)&wproj, g_wproj);
    cudaGetSymbolAddress((void**)&t0, g_t0);
    cudaGetSymbolAddress((void**)&t1, g_t1);
    cudaGetSymbolAddress((void**)&t2, g_t2);
    cudaGetSymbolAddress((void**)&t3, g_t3);
    cudaGetSymbolAddress((void**)&t4, g_t4);
    cudaGetSymbolAddress((void**)&part, g_part);
    cudaGetSymbolAddress((void**)&scale, g_scale);
    cudaGetSymbolAddress((void**)&shift, g_shift);

    // 1) hypernet weights
    {
        int tot = NHEADS * CPROJ * CIN0;
        hyper_kernel<<<(tot + 255) / 256, 256>>>(y_in, tables, wproj);
    }
    // 2) dynamic 1x1x1 projection -> t0 [2,1024,4,6,8]
    {
        int tot = BATCH * 1024 * 192;
        proj_kernel<<<(tot + 255) / 256, 256>>>(x_in, wproj, t0);
    }
    // 3) decoder stack
    run_bn(t0, 1024, 4 * 6 * 8, g0, be0, part, scale, shift);
    run_convt<false>(t0, w1, b1, t1, 1024, 512, 4, 6, 8);
    run_bn(t1, 512, 8 * 12 * 16, g1, be1, part, scale, shift);
    run_convt<false>(t1, w2, b2, t2, 512, 256, 8, 12, 16);
    run_bn(t2, 256, 16 * 24 * 32, g2, be2, part, scale, shift);
    run_convt<false>(t2, w3, b3, t3, 256, 128, 16, 24, 32);
    run_bn(t3, 128, 32 * 48 * 64, g3, be3, part, scale, shift);
    run_convt<false>(t3, w4, b4, t4, 128, 32, 32, 48, 64);
    run_bn(t4, 32, 64 * 96 * 128, g4, be4, part, scale, shift);
    run_convt<true>(t4, w5, b5, (float*)d_out, 32, 1, 64, 96, 128);
}

// round 5
// speedup vs baseline: 1.9884x; 1.9884x over previous
#include <cuda_runtime.h>
#include <math.h>

// ---------------- problem constants ----------------
#define BATCH 2
#define NCLS 24
#define NHEADS 8
#define CIN0 1024
#define CPROJ 128

// ---------------- scratch (static device memory; no allocs) ----------------
__device__ __align__(16) float g_wproj[(size_t)BATCH * NHEADS * CPROJ * CIN0];
__device__ __align__(16) float g_t0[(size_t)BATCH * 1024 * 4 * 6 * 8];
__device__ __align__(16) float g_t1[(size_t)BATCH * 512 * 8 * 12 * 16];
__device__ __align__(16) float g_t2[(size_t)BATCH * 256 * 16 * 24 * 32];
__device__ __align__(16) float g_t3[(size_t)BATCH * 128 * 32 * 48 * 64];
__device__ __align__(16) float g_t4[(size_t)BATCH * 32 * 64 * 96 * 128];
__device__ __align__(16) float g_part[1024 * 16 * 2];
__device__ __align__(16) float g_scale[1024];
__device__ __align__(16) float g_shift[1024];

// ---------------- hypernet ----------------
__global__ void hyper_kernel(const float* __restrict__ y,
                             const float* __restrict__ tables,
                             float* __restrict__ wout) {
    const int K = CPROJ * CIN0;
    int gid = blockIdx.x * blockDim.x + threadIdx.x;
    if (gid >= NHEADS * K) return;
    int h = gid / K;
    int k = gid - h * K;
    const float* t = tables + (size_t)h * NCLS * K + k;
    float a0 = 0.f, a1 = 0.f;
#pragma unroll
    for (int q = 0; q < NCLS; q++) {
        float tv = t[(size_t)q * K];
        a0 += y[q] * tv;
        a1 += y[NCLS + q] * tv;
    }
    wout[(size_t)0 * NHEADS * K + gid] = a0;
    wout[(size_t)1 * NHEADS * K + gid] = a1;
}

// ---------------- projection (smem-tiled, 8 out-rows per block) ----------------
__global__ void proj_kernel2(const float* __restrict__ x,
                             const float* __restrict__ w,
                             float* __restrict__ out) {
    const int S = 192;
    const int s = threadIdx.x;  // 0..191
    const int hb = blockIdx.x;  // 0..127
    const int b = blockIdx.y;
    const float* xb = x + (size_t)b * 1024 * S + s;
    const float* wb = w + ((size_t)b * 1024 + hb * 8) * 1024;

    __shared__ float wsh[8][192];
    float acc[8];
#pragma unroll
    for (int j = 0; j < 8; j++) acc[j] = 0.f;

    for (int c0 = 0; c0 < 1024; c0 += 192) {
        __syncthreads();
        int cmax = 1024 - c0 < 192 ? 1024 - c0 : 192;
        if (s < cmax) {
#pragma unroll
            for (int j = 0; j < 8; j++) wsh[j][s] = wb[(size_t)j * 1024 + c0 + s];
        }
        __syncthreads();
        for (int cc = 0; cc < cmax; cc++) {
            float xv = xb[(size_t)(c0 + cc) * S];
#pragma unroll
            for (int j = 0; j < 8; j++) acc[j] = fmaf(wsh[j][cc], xv, acc[j]);
        }
    }
#pragma unroll
    for (int j = 0; j < 8; j++)
        out[((size_t)b * 1024 + hb * 8 + j) * S + s] = acc[j];
}

// ---------------- BatchNorm ----------------
#define BN_NB 16
__global__ void bn_partial(const float* __restrict__ x, int C, int S,
                           float* __restrict__ part) {
    int c = blockIdx.x;
    int nb = blockIdx.y;
    int n = BATCH * S;
    float s1 = 0.f, s2 = 0.f;
    for (int e = nb * blockDim.x + threadIdx.x; e < n; e += BN_NB * blockDim.x) {
        int bb = e / S;
        int sp = e - bb * S;
        float v = x[((size_t)bb * C + c) * S + sp];
        s1 += v;
        s2 += v * v;
    }
    __shared__ float r1[256];
    __shared__ float r2[256];
    r1[threadIdx.x] = s1;
    r2[threadIdx.x] = s2;
    __syncthreads();
    for (int st = 128; st > 0; st >>= 1) {
        if (threadIdx.x < st) {
            r1[threadIdx.x] += r1[threadIdx.x + st];
            r2[threadIdx.x] += r2[threadIdx.x + st];
        }
        __syncthreads();
    }
    if (threadIdx.x == 0) {
        part[(c * BN_NB + nb) * 2 + 0] = r1[0];
        part[(c * BN_NB + nb) * 2 + 1] = r2[0];
    }
}

__global__ void bn_finalize(const float* __restrict__ part, int C, float n,
                            const float* __restrict__ g, const float* __restrict__ be,
                            float* __restrict__ scale, float* __restrict__ shift) {
    int c = blockIdx.x * blockDim.x + threadIdx.x;
    if (c >= C) return;
    float s1 = 0.f, s2 = 0.f;
    for (int i = 0; i < BN_NB; i++) {
        s1 += part[(c * BN_NB + i) * 2 + 0];
        s2 += part[(c * BN_NB + i) * 2 + 1];
    }
    float mean = s1 / n;
    float var = s2 / n - mean * mean;
    var = fmaxf(var, 0.f);
    float sc = g[c] * rsqrtf(var + 1e-5f);
    scale[c] = sc;
    shift[c] = be[c] - mean * sc;
}

__global__ void bn_apply_relu(float* __restrict__ x, int C, int S,
                              const float* __restrict__ scale,
                              const float* __restrict__ shift) {
    size_t gid = (size_t)blockIdx.x * blockDim.x + threadIdx.x;
    size_t total = (size_t)BATCH * C * S;
    if (gid >= total) return;
    int c = (int)((gid / S) % C);
    float v = fmaf(x[gid], scale[c], shift[c]);
    x[gid] = v > 0.f ? v : 0.f;
}

// ---------------- ConvTranspose3d k=4 s=2 p=1 : smem-staged, scalar FFMA ----------------
// out[o, 2m+p] gathers inputs m+DD[p][s] with tap KK[p][s] per dim:
//   p=0: (d=0,k=1),(d=-1,k=3) ; p=1: (d=+1,k=0),(d=0,k=2)
// Thread: 1 z x 2 y x 2 x input cells -> 32 outputs.
// Input tile staged in smem (halo zero-padded, double buffered).
// Weights staged in CC-channel chunks (double buffered), scalar broadcast reads.
// Compute core identical to the proven R2 kernel.
template <int TILEY, int TILEX, bool SIG>
__global__ void __launch_bounds__(TILEY * TILEX)
convt3_kernel(const float* __restrict__ in, const float* __restrict__ wt,
              const float* __restrict__ bias, float* __restrict__ out,
              int Cin, int Cout, int Dz, int Hy, int Wx, int ntx, int nty) {
    constexpr int TXc = TILEX / 2;
    constexpr int TYc = TILEY / 2;
    constexpr int NT = TILEY * TILEX;
    constexpr int PH = TILEY + 2;
    constexpr int PWD = TILEX + 2;
    constexpr int SDL = 6 * PH * PWD;
    constexpr int RMAX = (SDL + NT - 1) / NT;
    constexpr int CC = 32;  // weight chunk (channels)

    __shared__ float vsm[2][SDL];
    __shared__ float wsm[2][CC * 64];

    const int tid = threadIdx.x;
    const int o = blockIdx.y;
    const int b = blockIdx.z;
    const int tile = blockIdx.x;
    const int tix = tile % ntx;
    const int t2 = tile / ntx;
    const int tiy = t2 % nty;
    const int tiz = t2 / nty;

    const int txi = tid % TXc;
    const int t3 = tid / TXc;
    const int tyi = t3 % TYc;
    const int tzi = t3 / TYc;

    const int bz = tiz * 4, by = tiy * TILEY, bx = tix * TILEX;
    const int S = Dz * Hy * Wx;
    const float* inb = in + (size_t)b * Cin * S;

    // channel-invariant staging offsets
    int soff[RMAX];
    int sdst[RMAX];
    bool svld[RMAX];
    bool sact[RMAX];
#pragma unroll
    for (int r = 0; r < RMAX; r++) {
        int idx = tid + r * NT;
        sact[r] = idx < SDL;
        int i2 = sact[r] ? idx : 0;
        int pz_ = i2 / (PH * PWD);
        int rem = i2 - pz_ * (PH * PWD);
        int py_ = rem / PWD;
        int px_ = rem - py_ * PWD;
        int gz = bz + pz_ - 1, gy = by + py_ - 1, gx = bx + px_ - 1;
        bool v = (gz >= 0 && gz < Dz && gy >= 0 && gy < Hy && gx >= 0 && gx < Wx);
        svld[r] = v;
        soff[r] = v ? (gz * Hy + gy) * Wx + gx : 0;
        sdst[r] = i2;  // staged layout == logical padded layout
    }

    auto stage_v = [&](int c) {
        float* vb = vsm[c & 1];
        const float* pc = inb + (size_t)c * S;
#pragma unroll
        for (int r = 0; r < RMAX; r++) {
            if (sact[r]) vb[sdst[r]] = svld[r] ? pc[soff[r]] : 0.f;
        }
    };
    auto stage_w = [&](int chunk) {
        float* wd = wsm[chunk & 1];
        const float* wsrc = wt + ((size_t)(chunk * CC) * Cout + o) * 64;
        for (int i = tid; i < CC * 64; i += NT) {
            int cl = i >> 6;
            int k = i & 63;
            wd[i] = wsrc[(size_t)cl * Cout * 64 + k];
        }
    };

    float acc[2][2][8];
#pragma unroll
    for (int cy = 0; cy < 2; cy++)
#pragma unroll
        for (int cx = 0; cx < 2; cx++)
#pragma unroll
            for (int p = 0; p < 8; p++) acc[cy][cx][p] = 0.f;

    stage_w(0);
    stage_v(0);
    __syncthreads();

    const int tbase = (tzi * PH + 2 * tyi) * PWD + 2 * txi;
    const int DDt[2][2] = {{0, -1}, {1, 0}};
    const int KKt[2][2] = {{1, 3}, {0, 2}};

    for (int c = 0; c < Cin; c++) {
        if (c + 1 < Cin) stage_v(c + 1);
        if ((c & (CC - 1)) == 0 && c + CC < Cin) stage_w(c / CC + 1);

        const float* vb = vsm[c & 1];
        const float* wc = wsm[(c / CC) & 1] + (c & (CC - 1)) * 64;

        float v[3][4][4];
#pragma unroll
        for (int jz = 0; jz < 3; jz++)
#pragma unroll
            for (int jy = 0; jy < 4; jy++)
#pragma unroll
                for (int jx = 0; jx < 4; jx++)
                    v[jz][jy][jx] = vb[tbase + (jz * PH + jy) * PWD + jx];

#pragma unroll
        for (int pz = 0; pz < 2; pz++)
#pragma unroll
            for (int sz = 0; sz < 2; sz++) {
                const int jz = 1 + DDt[pz][sz];
                const int kz = KKt[pz][sz];
#pragma unroll
                for (int py = 0; py < 2; py++)
#pragma unroll
                    for (int sy = 0; sy < 2; sy++) {
                        const int jy0 = 1 + DDt[py][sy];
                        const int ky = KKt[py][sy];
#pragma unroll
                        for (int px = 0; px < 2; px++)
#pragma unroll
                            for (int sx = 0; sx < 2; sx++) {
                                const int jx0 = 1 + DDt[px][sx];
                                const int kx = KKt[px][sx];
                                const float wv = wc[kz * 16 + ky * 4 + kx];
                                const int p = pz * 4 + py * 2 + px;
#pragma unroll
                                for (int cy = 0; cy < 2; cy++)
#pragma unroll
                                    for (int cx = 0; cx < 2; cx++)
                                        acc[cy][cx][p] = fmaf(
                                            v[jz][cy + jy0][cx + jx0], wv,
                                            acc[cy][cx][p]);
                            }
                    }
            }
        __syncthreads();
    }

    // ---------------- epilogue (scalar stores, proven in R2) ----------------
    const int mz = bz + tzi;
    if (mz >= Dz) return;
    const float bv = bias[o];
    const int Ho = 2 * Hy, Wo = 2 * Wx;
    float* ob = out + ((size_t)b * Cout + o) * (size_t)(2 * Dz) * Ho * Wo;
    const int my0 = by + 2 * tyi;
    const int mx0 = bx + 2 * txi;

#pragma unroll
    for (int cy = 0; cy < 2; cy++) {
        int my = my0 + cy;
        if (my >= Hy) continue;
#pragma unroll
        for (int cx = 0; cx < 2; cx++) {
            int mx = mx0 + cx;
            if (mx >= Wx) continue;
#pragma unroll
            for (int pz = 0; pz < 2; pz++)
#pragma unroll
                for (int py = 0; py < 2; py++)
#pragma unroll
                    for (int px = 0; px < 2; px++) {
                        float r = acc[cy][cx][pz * 4 + py * 2 + px] + bv;
                        if (SIG) r = 1.f / (1.f + expf(-r));
                        ob[(size_t)(2 * mz + pz) * Ho * Wo +
                           (size_t)(2 * my + py) * Wo + (2 * mx + px)] = r;
                    }
        }
    }
}

// ---------------- host-side helpers ----------------
static void run_bn(float* t, int C, int S, const float* g, const float* be,
                   float* part, float* scale, float* shift) {
    dim3 gp(C, BN_NB);
    bn_partial<<<gp, 256>>>(t, C, S, part);
    bn_finalize<<<(C + 127) / 128, 128>>>(part, C, (float)(BATCH * S), g, be, scale, shift);
    size_t total = (size_t)BATCH * C * S;
    bn_apply_relu<<<(unsigned)((total + 255) / 256), 256>>>(t, C, S, scale, shift);
}

template <int TILEY, int TILEX, bool SIG>
static void run_convt3(const float* in, const float* wt, const float* bias,
                       float* out, int Cin, int Cout, int Dz, int Hy, int Wx) {
    int ntx = (Wx + TILEX - 1) / TILEX;
    int nty = (Hy + TILEY - 1) / TILEY;
    int ntz = (Dz + 3) / 4;
    dim3 grid(ntx * nty * ntz, Cout, BATCH);
    convt3_kernel<TILEY, TILEX, SIG>
        <<<grid, TILEY * TILEX>>>(in, wt, bias, out, Cin, Cout, Dz, Hy, Wx, ntx, nty);
}

extern "C" void kernel_launch(void* const* d_in, const int* in_sizes, int n_in,
                              void* d_out, int out_size) {
    const float* x_in = (const float*)d_in[0];
    const float* y_in = (const float*)d_in[1];
    const float* tables = (const float*)d_in[2];
    const float* g0 = (const float*)d_in[3];
    const float* be0 = (const float*)d_in[4];
    const float* g1 = (const float*)d_in[5];
    const float* be1 = (const float*)d_in[6];
    const float* g2 = (const float*)d_in[7];
    const float* be2 = (const float*)d_in[8];
    const float* g3 = (const float*)d_in[9];
    const float* be3 = (const float*)d_in[10];
    const float* g4 = (const float*)d_in[11];
    const float* be4 = (const float*)d_in[12];
    const float* w1 = (const float*)d_in[13];
    const float* b1 = (const float*)d_in[14];
    const float* w2 = (const float*)d_in[15];
    const float* b2 = (const float*)d_in[16];
    const float* w3 = (const float*)d_in[17];
    const float* b3 = (const float*)d_in[18];
    const float* w4 = (const float*)d_in[19];
    const float* b4 = (const float*)d_in[20];
    const float* w5 = (const float*)d_in[21];
    const float* b5 = (const float*)d_in[22];

    float *wproj, *t0, *t1, *t2, *t3, *t4, *part, *scale, *shift;
    cudaGetSymbolAddress((void**)&wproj, g_wproj);
    cudaGetSymbolAddress((void**)&t0, g_t0);
    cudaGetSymbolAddress((void**)&t1, g_t1);
    cudaGetSymbolAddress((void**)&t2, g_t2);
    cudaGetSymbolAddress((void**)&t3, g_t3);
    cudaGetSymbolAddress((void**)&t4, g_t4);
    cudaGetSymbolAddress((void**)&part, g_part);
    cudaGetSymbolAddress((void**)&scale, g_scale);
    cudaGetSymbolAddress((void**)&shift, g_shift);

    // 1) hypernet weights
    {
        int tot = NHEADS * CPROJ * CIN0;
        hyper_kernel<<<(tot + 255) / 256, 256>>>(y_in, tables, wproj);
    }
    // 2) dynamic 1x1x1 projection -> t0 [2,1024,4,6,8]
    {
        dim3 pg(128, BATCH);
        proj_kernel2<<<pg, 192>>>(x_in, wproj, t0);
    }
    // 3) decoder stack
    run_bn(t0, 1024, 4 * 6 * 8, g0, be0, part, scale, shift);
    run_convt3<6, 8, false>(t0, w1, b1, t1, 1024, 512, 4, 6, 8);
    run_bn(t1, 512, 8 * 12 * 16, g1, be1, part, scale, shift);
    run_convt3<12, 16, false>(t1, w2, b2, t2, 512, 256, 8, 12, 16);
    run_bn(t2, 256, 16 * 24 * 32, g2, be2, part, scale, shift);
    run_convt3<12, 16, false>(t2, w3, b3, t3, 256, 128, 16, 24, 32);
    run_bn(t3, 128, 32 * 48 * 64, g3, be3, part, scale, shift);
    run_convt3<12, 16, false>(t3, w4, b4, t4, 128, 32, 32, 48, 64);
    run_bn(t4, 32, 64 * 96 * 128, g4, be4, part, scale, shift);
    run_convt3<12, 16, true>(t4, w5, b5, (float*)d_out, 32, 1, 64, 96, 128);
}

// round 6
// speedup vs baseline: 2.1909x; 1.1019x over previous
#include <cuda_runtime.h>
#include <math.h>

// ---------------- problem constants ----------------
#define BATCH 2
#define NCLS 24
#define NHEADS 8
#define CIN0 1024
#define CPROJ 128

typedef unsigned long long ull;

// ---------------- scratch (static device memory; no allocs) ----------------
__device__ __align__(16) float g_wproj[(size_t)BATCH * NHEADS * CPROJ * CIN0];
__device__ __align__(16) float g_t0[(size_t)BATCH * 1024 * 4 * 6 * 8];
__device__ __align__(16) float g_t1[(size_t)BATCH * 512 * 8 * 12 * 16];
__device__ __align__(16) float g_t2[(size_t)BATCH * 256 * 16 * 24 * 32];
__device__ __align__(16) float g_t3[(size_t)BATCH * 128 * 32 * 48 * 64];
__device__ __align__(16) float g_t4[(size_t)BATCH * 32 * 64 * 96 * 128];
__device__ __align__(16) float g_part[1024 * 16 * 2];
__device__ __align__(16) float g_scale[1024];
__device__ __align__(16) float g_shift[1024];

// ---------------- packed f32x2 helpers (register-only) ----------------
__device__ __forceinline__ void fma2(ull& d, ull a, ull b) {
    asm("fma.rn.f32x2 %0, %1, %2, %0;" : "+l"(d) : "l"(a), "l"(b));
}
__device__ __forceinline__ ull pack2f(float lo, float hi) {
    ull r;
    asm("mov.b64 %0, {%1, %2};" : "=l"(r) : "f"(lo), "f"(hi));
    return r;
}
__device__ __forceinline__ float2 unpk2(ull v) {
    float2 r;
    asm("mov.b64 {%0, %1}, %2;" : "=f"(r.x), "=f"(r.y) : "l"(v));
    return r;
}

// ---------------- hypernet ----------------
__global__ void hyper_kernel(const float* __restrict__ y,
                             const float* __restrict__ tables,
                             float* __restrict__ wout) {
    const int K = CPROJ * CIN0;
    int gid = blockIdx.x * blockDim.x + threadIdx.x;
    if (gid >= NHEADS * K) return;
    int h = gid / K;
    int k = gid - h * K;
    const float* t = tables + (size_t)h * NCLS * K + k;
    float a0 = 0.f, a1 = 0.f;
#pragma unroll
    for (int q = 0; q < NCLS; q++) {
        float tv = t[(size_t)q * K];
        a0 += y[q] * tv;
        a1 += y[NCLS + q] * tv;
    }
    wout[(size_t)0 * NHEADS * K + gid] = a0;
    wout[(size_t)1 * NHEADS * K + gid] = a1;
}

// ---------------- projection (smem-tiled, 8 out-rows per block) ----------------
__global__ void proj_kernel2(const float* __restrict__ x,
                             const float* __restrict__ w,
                             float* __restrict__ out) {
    const int S = 192;
    const int s = threadIdx.x;  // 0..191
    const int hb = blockIdx.x;  // 0..127
    const int b = blockIdx.y;
    const float* xb = x + (size_t)b * 1024 * S + s;
    const float* wb = w + ((size_t)b * 1024 + hb * 8) * 1024;

    __shared__ float wsh[8][192];
    float acc[8];
#pragma unroll
    for (int j = 0; j < 8; j++) acc[j] = 0.f;

    for (int c0 = 0; c0 < 1024; c0 += 192) {
        __syncthreads();
        int cmax = 1024 - c0 < 192 ? 1024 - c0 : 192;
        if (s < cmax) {
#pragma unroll
            for (int j = 0; j < 8; j++) wsh[j][s] = wb[(size_t)j * 1024 + c0 + s];
        }
        __syncthreads();
        for (int cc = 0; cc < cmax; cc++) {
            float xv = xb[(size_t)(c0 + cc) * S];
#pragma unroll
            for (int j = 0; j < 8; j++) acc[j] = fmaf(wsh[j][cc], xv, acc[j]);
        }
    }
#pragma unroll
    for (int j = 0; j < 8; j++)
        out[((size_t)b * 1024 + hb * 8 + j) * S + s] = acc[j];
}

// ---------------- BatchNorm ----------------
#define BN_NB 16
__global__ void bn_partial(const float* __restrict__ x, int C, int S,
                           float* __restrict__ part) {
    int c = blockIdx.x;
    int nb = blockIdx.y;
    int n = BATCH * S;
    float s1 = 0.f, s2 = 0.f;
    for (int e = nb * blockDim.x + threadIdx.x; e < n; e += BN_NB * blockDim.x) {
        int bb = e / S;
        int sp = e - bb * S;
        float v = x[((size_t)bb * C + c) * S + sp];
        s1 += v;
        s2 += v * v;
    }
    __shared__ float r1[256];
    __shared__ float r2[256];
    r1[threadIdx.x] = s1;
    r2[threadIdx.x] = s2;
    __syncthreads();
    for (int st = 128; st > 0; st >>= 1) {
        if (threadIdx.x < st) {
            r1[threadIdx.x] += r1[threadIdx.x + st];
            r2[threadIdx.x] += r2[threadIdx.x + st];
        }
        __syncthreads();
    }
    if (threadIdx.x == 0) {
        part[(c * BN_NB + nb) * 2 + 0] = r1[0];
        part[(c * BN_NB + nb) * 2 + 1] = r2[0];
    }
}

__global__ void bn_finalize(const float* __restrict__ part, int C, float n,
                            const float* __restrict__ g, const float* __restrict__ be,
                            float* __restrict__ scale, float* __restrict__ shift) {
    int c = blockIdx.x * blockDim.x + threadIdx.x;
    if (c >= C) return;
    float s1 = 0.f, s2 = 0.f;
    for (int i = 0; i < BN_NB; i++) {
        s1 += part[(c * BN_NB + i) * 2 + 0];
        s2 += part[(c * BN_NB + i) * 2 + 1];
    }
    float mean = s1 / n;
    float var = s2 / n - mean * mean;
    var = fmaxf(var, 0.f);
    float sc = g[c] * rsqrtf(var + 1e-5f);
    scale[c] = sc;
    shift[c] = be[c] - mean * sc;
}

__global__ void bn_apply_relu(float* __restrict__ x, int C, int S,
                              const float* __restrict__ scale,
                              const float* __restrict__ shift) {
    size_t gid = (size_t)blockIdx.x * blockDim.x + threadIdx.x;
    size_t total = (size_t)BATCH * C * S;
    if (gid >= total) return;
    int c = (int)((gid / S) % C);
    float v = fmaf(x[gid], scale[c], shift[c]);
    x[gid] = v > 0.f ? v : 0.f;
}

// ---------------- ConvTranspose3d k=4 s=2 p=1 : smem-staged, f32x2 over px ----------------
// Per dim: out px=0 taps (d=0,k=1),(d=-1,k=3) ; px=1 taps (d=+1,k=0),(d=0,k=2).
// Cell at input m: px0 += v[m]*w1 + v[m-1]*w3 ; px1 += v[m+1]*w0 + v[m]*w2
//   => FMA2((v[m],v[m+1]), (w1,w0)) + FMA2((v[m-1],v[m]), (w3,w2))
// Weights pre-paired at stage time into typed float2 smem.
// Skeleton (staging, scalar v loads, epilogue) identical to the passing R5 kernel.
template <int TILEY, int TILEX, bool SIG>
__global__ void __launch_bounds__(TILEY * TILEX)
convt4_kernel(const float* __restrict__ in, const float* __restrict__ wt,
              const float* __restrict__ bias, float* __restrict__ out,
              int Cin, int Cout, int Dz, int Hy, int Wx, int ntx, int nty) {
    constexpr int TXc = TILEX / 2;
    constexpr int TYc = TILEY / 2;
    constexpr int NT = TILEY * TILEX;
    constexpr int PH = TILEY + 2;
    constexpr int PWD = TILEX + 2;
    constexpr int SDL = 6 * PH * PWD;
    constexpr int RMAX = (SDL + NT - 1) / NT;
    constexpr int CC = 32;  // weight chunk (channels)

    __shared__ float vsm[2][SDL];
    __shared__ __align__(16) float2 wsm2[2][CC * 32];  // per channel: 16 (kz,ky) x 2 pairs

    const int tid = threadIdx.x;
    const int o = blockIdx.y;
    const int b = blockIdx.z;
    const int tile = blockIdx.x;
    const int tix = tile % ntx;
    const int t2 = tile / ntx;
    const int tiy = t2 % nty;
    const int tiz = t2 / nty;

    const int txi = tid % TXc;
    const int t3 = tid / TXc;
    const int tyi = t3 % TYc;
    const int tzi = t3 / TYc;

    const int bz = tiz * 4, by = tiy * TILEY, bx = tix * TILEX;
    const int S = Dz * Hy * Wx;
    const float* inb = in + (size_t)b * Cin * S;

    // channel-invariant staging offsets (identical to R5)
    int soff[RMAX];
    bool svld[RMAX];
    bool sact[RMAX];
    int sdst[RMAX];
#pragma unroll
    for (int r = 0; r < RMAX; r++) {
        int idx = tid + r * NT;
        sact[r] = idx < SDL;
        int i2 = sact[r] ? idx : 0;
        int pz_ = i2 / (PH * PWD);
        int rem = i2 - pz_ * (PH * PWD);
        int py_ = rem / PWD;
        int px_ = rem - py_ * PWD;
        int gz = bz + pz_ - 1, gy = by + py_ - 1, gx = bx + px_ - 1;
        bool v = (gz >= 0 && gz < Dz && gy >= 0 && gy < Hy && gx >= 0 && gx < Wx);
        svld[r] = v;
        soff[r] = v ? (gz * Hy + gy) * Wx + gx : 0;
        sdst[r] = i2;
    }

    auto stage_v = [&](int c) {
        float* vb = vsm[c & 1];
        const float* pc = inb + (size_t)c * S;
#pragma unroll
        for (int r = 0; r < RMAX; r++) {
            if (sact[r]) vb[sdst[r]] = svld[r] ? pc[soff[r]] : 0.f;
        }
    };
    // stage weights pre-paired: entry (cl, kzky, half):
    //   half 0 -> (w_kx1, w_kx0), half 1 -> (w_kx3, w_kx2)
    auto stage_w = [&](int chunk) {
        float2* wd = wsm2[chunk & 1];
        const float* wsrc = wt + ((size_t)(chunk * CC) * Cout + o) * 64;
        for (int i = tid; i < CC * 32; i += NT) {
            int cl = i >> 5;
            int e = i & 31;
            int kzky = e >> 1;
            int half = e & 1;
            const float* wk = wsrc + (size_t)cl * Cout * 64 + kzky * 4;
            float2 p;
            if (half == 0) { p.x = wk[1]; p.y = wk[0]; }
            else           { p.x = wk[3]; p.y = wk[2]; }
            wd[i] = p;
        }
    };

    ull acc[2][2][4];  // [cy][cx][pz*2+py] = (px0, px1)
#pragma unroll
    for (int cy = 0; cy < 2; cy++)
#pragma unroll
        for (int cx = 0; cx < 2; cx++)
#pragma unroll
            for (int p = 0; p < 4; p++) acc[cy][cx][p] = 0ull;

    stage_w(0);
    stage_v(0);
    __syncthreads();

    const int tbase = (tzi * PH + 2 * tyi) * PWD + 2 * txi;
    const int DDt[2][2] = {{0, -1}, {1, 0}};
    const int KKt[2][2] = {{1, 3}, {0, 2}};

    for (int c = 0; c < Cin; c++) {
        if (c + 1 < Cin) stage_v(c + 1);
        if ((c & (CC - 1)) == 0 && c + CC < Cin) stage_w(c / CC + 1);

        const float* vb = vsm[c & 1];
        const float2* wc2 = wsm2[(c / CC) & 1] + (c & (CC - 1)) * 32;

#pragma unroll
        for (int jz = 0; jz < 3; jz++) {
            // scalar loads (proven path), register-only packs
            ull vp[4][3];
#pragma unroll
            for (int ry = 0; ry < 4; ry++) {
                float x0 = vb[tbase + (jz * PH + ry) * PWD + 0];
                float x1 = vb[tbase + (jz * PH + ry) * PWD + 1];
                float x2 = vb[tbase + (jz * PH + ry) * PWD + 2];
                float x3 = vb[tbase + (jz * PH + ry) * PWD + 3];
                vp[ry][0] = pack2f(x0, x1);
                vp[ry][1] = pack2f(x1, x2);
                vp[ry][2] = pack2f(x2, x3);
            }
#pragma unroll
            for (int pz = 0; pz < 2; pz++)
#pragma unroll
                for (int sz = 0; sz < 2; sz++) {
                    if (1 + DDt[pz][sz] != jz) continue;  // compile-time pruned
                    const int kz = KKt[pz][sz];
#pragma unroll
                    for (int py = 0; py < 2; py++)
#pragma unroll
                        for (int sy = 0; sy < 2; sy++) {
                            const int jy0 = 1 + DDt[py][sy];
                            const int ky = KKt[py][sy];
                            const float2 wA = wc2[(kz * 4 + ky) * 2 + 0];  // (w1,w0)
                            const float2 wB = wc2[(kz * 4 + ky) * 2 + 1];  // (w3,w2)
                            const ull wa = pack2f(wA.x, wA.y);
                            const ull wb = pack2f(wB.x, wB.y);
#pragma unroll
                            for (int cy = 0; cy < 2; cy++) {
                                const int row = jy0 + cy;
#pragma unroll
                                for (int cx = 0; cx < 2; cx++) {
                                    fma2(acc[cy][cx][pz * 2 + py], vp[row][cx + 1], wa);
                                    fma2(acc[cy][cx][pz * 2 + py], vp[row][cx], wb);
                                }
                            }
                        }
                }
        }
        __syncthreads();
    }

    // ---------------- epilogue (scalar stores, as R5) ----------------
    const int mz = bz + tzi;
    if (mz >= Dz) return;
    const float bv = bias[o];
    const int Ho = 2 * Hy, Wo = 2 * Wx;
    float* ob = out + ((size_t)b * Cout + o) * (size_t)(2 * Dz) * Ho * Wo;
    const int my0 = by + 2 * tyi;
    const int mx0 = bx + 2 * txi;

#pragma unroll
    for (int cy = 0; cy < 2; cy++) {
        int my = my0 + cy;
        if (my >= Hy) continue;
#pragma unroll
        for (int cx = 0; cx < 2; cx++) {
            int mx = mx0 + cx;
            if (mx >= Wx) continue;
#pragma unroll
            for (int pz = 0; pz < 2; pz++)
#pragma unroll
                for (int py = 0; py < 2; py++) {
                    float2 a = unpk2(acc[cy][cx][pz * 2 + py]);
                    float r0 = a.x + bv;
                    float r1 = a.y + bv;
                    if (SIG) {
                        r0 = 1.f / (1.f + expf(-r0));
                        r1 = 1.f / (1.f + expf(-r1));
                    }
                    size_t base = (size_t)(2 * mz + pz) * Ho * Wo +
                                  (size_t)(2 * my + py) * Wo + (size_t)(2 * mx);
                    ob[base] = r0;
                    ob[base + 1] = r1;
                }
        }
    }
}

// ---------------- host-side helpers ----------------
static void run_bn(float* t, int C, int S, const float* g, const float* be,
                   float* part, float* scale, float* shift) {
    dim3 gp(C, BN_NB);
    bn_partial<<<gp, 256>>>(t, C, S, part);
    bn_finalize<<<(C + 127) / 128, 128>>>(part, C, (float)(BATCH * S), g, be, scale, shift);
    size_t total = (size_t)BATCH * C * S;
    bn_apply_relu<<<(unsigned)((total + 255) / 256), 256>>>(t, C, S, scale, shift);
}

template <int TILEY, int TILEX, bool SIG>
static void run_convt4(const float* in, const float* wt, const float* bias,
                       float* out, int Cin, int Cout, int Dz, int Hy, int Wx) {
    int ntx = (Wx + TILEX - 1) / TILEX;
    int nty = (Hy + TILEY - 1) / TILEY;
    int ntz = (Dz + 3) / 4;
    dim3 grid(ntx * nty * ntz, Cout, BATCH);
    convt4_kernel<TILEY, TILEX, SIG>
        <<<grid, TILEY * TILEX>>>(in, wt, bias, out, Cin, Cout, Dz, Hy, Wx, ntx, nty);
}

extern "C" void kernel_launch(void* const* d_in, const int* in_sizes, int n_in,
                              void* d_out, int out_size) {
    const float* x_in = (const float*)d_in[0];
    const float* y_in = (const float*)d_in[1];
    const float* tables = (const float*)d_in[2];
    const float* g0 = (const float*)d_in[3];
    const float* be0 = (const float*)d_in[4];
    const float* g1 = (const float*)d_in[5];
    const float* be1 = (const float*)d_in[6];
    const float* g2 = (const float*)d_in[7];
    const float* be2 = (const float*)d_in[8];
    const float* g3 = (const float*)d_in[9];
    const float* be3 = (const float*)d_in[10];
    const float* g4 = (const float*)d_in[11];
    const float* be4 = (const float*)d_in[12];
    const float* w1 = (const float*)d_in[13];
    const float* b1 = (const float*)d_in[14];
    const float* w2 = (const float*)d_in[15];
    const float* b2 = (const float*)d_in[16];
    const float* w3 = (const float*)d_in[17];
    const float* b3 = (const float*)d_in[18];
    const float* w4 = (const float*)d_in[19];
    const float* b4 = (const float*)d_in[20];
    const float* w5 = (const float*)d_in[21];
    const float* b5 = (const float*)d_in[22];

    float *wproj, *t0, *t1, *t2, *t3, *t4, *part, *scale, *shift;
    cudaGetSymbolAddress((void**)&wproj, g_wproj);
    cudaGetSymbolAddress((void**)&t0, g_t0);
    cudaGetSymbolAddress((void**)&t1, g_t1);
    cudaGetSymbolAddress((void**)&t2, g_t2);
    cudaGetSymbolAddress((void**)&t3, g_t3);
    cudaGetSymbolAddress((void**)&t4, g_t4);
    cudaGetSymbolAddress((void**)&part, g_part);
    cudaGetSymbolAddress((void**)&scale, g_scale);
    cudaGetSymbolAddress((void**)&shift, g_shift);

    // 1) hypernet weights
    {
        int tot = NHEADS * CPROJ * CIN0;
        hyper_kernel<<<(tot + 255) / 256, 256>>>(y_in, tables, wproj);
    }
    // 2) dynamic 1x1x1 projection -> t0 [2,1024,4,6,8]
    {
        dim3 pg(128, BATCH);
        proj_kernel2<<<pg, 192>>>(x_in, wproj, t0);
    }
    // 3) decoder stack
    run_bn(t0, 1024, 4 * 6 * 8, g0, be0, part, scale, shift);
    run_convt4<6, 8, false>(t0, w1, b1, t1, 1024, 512, 4, 6, 8);
    run_bn(t1, 512, 8 * 12 * 16, g1, be1, part, scale, shift);
    run_convt4<12, 16, false>(t1, w2, b2, t2, 512, 256, 8, 12, 16);
    run_bn(t2, 256, 16 * 24 * 32, g2, be2, part, scale, shift);
    run_convt4<12, 16, false>(t2, w3, b3, t3, 256, 128, 16, 24, 32);
    run_bn(t3, 128, 32 * 48 * 64, g3, be3, part, scale, shift);
    run_convt4<12, 16, false>(t3, w4, b4, t4, 128, 32, 32, 48, 64);
    run_bn(t4, 32, 64 * 96 * 128, g4, be4, part, scale, shift);
    run_convt4<12, 16, true>(t4, w5, b5, (float*)d_out, 32, 1, 64, 96, 128);
}

// round 7
// speedup vs baseline: 2.2965x; 1.0482x over previous
#include <cuda_runtime.h>
#include <math.h>

// ---------------- problem constants ----------------
#define BATCH 2
#define NCLS 24
#define NHEADS 8
#define CIN0 1024
#define CPROJ 128

typedef unsigned long long ull;

// ---------------- scratch (static device memory; no allocs) ----------------
__device__ __align__(16) float g_wproj[(size_t)BATCH * NHEADS * CPROJ * CIN0];
__device__ __align__(16) float g_t0[(size_t)BATCH * 1024 * 4 * 6 * 8];
__device__ __align__(16) float g_t1[(size_t)BATCH * 512 * 8 * 12 * 16];
__device__ __align__(16) float g_t2[(size_t)BATCH * 256 * 16 * 24 * 32];
__device__ __align__(16) float g_t3[(size_t)BATCH * 128 * 32 * 48 * 64];
__device__ __align__(16) float g_t4[(size_t)BATCH * 32 * 64 * 96 * 128];
__device__ __align__(16) float g_part[1024 * 16 * 2];
__device__ __align__(16) float g_scale[1024];
__device__ __align__(16) float g_shift[1024];

// ---------------- packed f32x2 helpers (register-only) ----------------
__device__ __forceinline__ void fma2(ull& d, ull a, ull b) {
    asm("fma.rn.f32x2 %0, %1, %2, %0;" : "+l"(d) : "l"(a), "l"(b));
}
__device__ __forceinline__ ull pack2f(float lo, float hi) {
    ull r;
    asm("mov.b64 %0, {%1, %2};" : "=l"(r) : "f"(lo), "f"(hi));
    return r;
}
__device__ __forceinline__ float2 unpk2(ull v) {
    float2 r;
    asm("mov.b64 {%0, %1}, %2;" : "=f"(r.x), "=f"(r.y) : "l"(v));
    return r;
}

// ---------------- hypernet ----------------
__global__ void hyper_kernel(const float* __restrict__ y,
                             const float* __restrict__ tables,
                             float* __restrict__ wout) {
    const int K = CPROJ * CIN0;
    int gid = blockIdx.x * blockDim.x + threadIdx.x;
    if (gid >= NHEADS * K) return;
    int h = gid / K;
    int k = gid - h * K;
    const float* t = tables + (size_t)h * NCLS * K + k;
    float a0 = 0.f, a1 = 0.f;
#pragma unroll
    for (int q = 0; q < NCLS; q++) {
        float tv = t[(size_t)q * K];
        a0 += y[q] * tv;
        a1 += y[NCLS + q] * tv;
    }
    wout[(size_t)0 * NHEADS * K + gid] = a0;
    wout[(size_t)1 * NHEADS * K + gid] = a1;
}

// ---------------- projection (smem-tiled, 8 out-rows per block) ----------------
__global__ void proj_kernel2(const float* __restrict__ x,
                             const float* __restrict__ w,
                             float* __restrict__ out) {
    const int S = 192;
    const int s = threadIdx.x;  // 0..191
    const int hb = blockIdx.x;  // 0..127
    const int b = blockIdx.y;
    const float* xb = x + (size_t)b * 1024 * S + s;
    const float* wb = w + ((size_t)b * 1024 + hb * 8) * 1024;

    __shared__ float wsh[8][192];
    float acc[8];
#pragma unroll
    for (int j = 0; j < 8; j++) acc[j] = 0.f;

    for (int c0 = 0; c0 < 1024; c0 += 192) {
        __syncthreads();
        int cmax = 1024 - c0 < 192 ? 1024 - c0 : 192;
        if (s < cmax) {
#pragma unroll
            for (int j = 0; j < 8; j++) wsh[j][s] = wb[(size_t)j * 1024 + c0 + s];
        }
        __syncthreads();
        for (int cc = 0; cc < cmax; cc++) {
            float xv = xb[(size_t)(c0 + cc) * S];
#pragma unroll
            for (int j = 0; j < 8; j++) acc[j] = fmaf(wsh[j][cc], xv, acc[j]);
        }
    }
#pragma unroll
    for (int j = 0; j < 8; j++)
        out[((size_t)b * 1024 + hb * 8 + j) * S + s] = acc[j];
}

// ---------------- BatchNorm ----------------
#define BN_NB 16
__global__ void bn_partial(const float* __restrict__ x, int C, int S,
                           float* __restrict__ part) {
    int c = blockIdx.x;
    int nb = blockIdx.y;
    int n = BATCH * S;
    float s1 = 0.f, s2 = 0.f;
    for (int e = nb * blockDim.x + threadIdx.x; e < n; e += BN_NB * blockDim.x) {
        int bb = e / S;
        int sp = e - bb * S;
        float v = x[((size_t)bb * C + c) * S + sp];
        s1 += v;
        s2 += v * v;
    }
    __shared__ float r1[256];
    __shared__ float r2[256];
    r1[threadIdx.x] = s1;
    r2[threadIdx.x] = s2;
    __syncthreads();
    for (int st = 128; st > 0; st >>= 1) {
        if (threadIdx.x < st) {
            r1[threadIdx.x] += r1[threadIdx.x + st];
            r2[threadIdx.x] += r2[threadIdx.x + st];
        }
        __syncthreads();
    }
    if (threadIdx.x == 0) {
        part[(c * BN_NB + nb) * 2 + 0] = r1[0];
        part[(c * BN_NB + nb) * 2 + 1] = r2[0];
    }
}

__global__ void bn_finalize(const float* __restrict__ part, int C, float n,
                            const float* __restrict__ g, const float* __restrict__ be,
                            float* __restrict__ scale, float* __restrict__ shift) {
    int c = blockIdx.x * blockDim.x + threadIdx.x;
    if (c >= C) return;
    float s1 = 0.f, s2 = 0.f;
    for (int i = 0; i < BN_NB; i++) {
        s1 += part[(c * BN_NB + i) * 2 + 0];
        s2 += part[(c * BN_NB + i) * 2 + 1];
    }
    float mean = s1 / n;
    float var = s2 / n - mean * mean;
    var = fmaxf(var, 0.f);
    float sc = g[c] * rsqrtf(var + 1e-5f);
    scale[c] = sc;
    shift[c] = be[c] - mean * sc;
}

__global__ void bn_apply_relu(float* __restrict__ x, int C, int S,
                              const float* __restrict__ scale,
                              const float* __restrict__ shift) {
    size_t gid = (size_t)blockIdx.x * blockDim.x + threadIdx.x;
    size_t total = (size_t)BATCH * C * S;
    if (gid >= total) return;
    int c = (int)((gid / S) % C);
    float v = fmaf(x[gid], scale[c], shift[c]);
    x[gid] = v > 0.f ? v : 0.f;
}

// ---------------- ConvTranspose3d k=4 s=2 p=1 : f32x2, prefetch, OG outputs/block ----
// Per dim: out px=0 taps (d=0,k=1),(d=-1,k=3) ; px=1 taps (d=+1,k=0),(d=0,k=2).
// Cell m: px0 += v[m]*w1 + v[m-1]*w3 ; px1 += v[m+1]*w0 + v[m]*w2
//   => FMA2((v[m],v[m+1]), (w1,w0)) + FMA2((v[m-1],v[m]), (w3,w2))
// Weights stored in smem as pre-packed ull pairs (no inner-loop repacking).
// Input channel c+1 prefetched into registers at loop top; STS'd after compute.
// OG output channels share one staged v-tile per block (L1 uses OG=2).
template <int TILEY, int TILEX, int OG, int CC, bool SIG>
__global__ void __launch_bounds__(TILEY * TILEX * OG)
convt5_kernel(const float* __restrict__ in, const float* __restrict__ wt,
              const float* __restrict__ bias, float* __restrict__ out,
              int Cin, int Cout, int Dz, int Hy, int Wx, int ntx, int nty) {
    constexpr int TXc = TILEX / 2;
    constexpr int TYc = TILEY / 2;
    constexpr int NTS = TILEY * TILEX;
    constexpr int NT = NTS * OG;
    constexpr int PH = TILEY + 2;
    constexpr int PWD = TILEX + 2;
    constexpr int SDL = 6 * PH * PWD;
    constexpr int RMAX = (SDL + NT - 1) / NT;
    constexpr int WPC = OG * CC * 32;  // packed ull weight entries per chunk

    __shared__ float vsm[2][SDL];
    __shared__ ull wsmU[2][WPC];

    const int tid = threadIdx.x;
    const int og = tid / NTS;
    const int s = tid - og * NTS;
    const int o = blockIdx.y * OG + og;
    const int b = blockIdx.z;
    const int tile = blockIdx.x;
    const int tix = tile % ntx;
    const int t2 = tile / ntx;
    const int tiy = t2 % nty;
    const int tiz = t2 / nty;

    const int txi = s % TXc;
    const int t3 = s / TXc;
    const int tyi = t3 % TYc;
    const int tzi = t3 / TYc;

    const int bz = tiz * 4, by = tiy * TILEY, bx = tix * TILEX;
    const int S = Dz * Hy * Wx;
    const float* inb = in + (size_t)b * Cin * S;

    // channel-invariant staging offsets
    int soff[RMAX];
    bool svld[RMAX];
    bool sact[RMAX];
    int sdst[RMAX];
#pragma unroll
    for (int r = 0; r < RMAX; r++) {
        int idx = tid + r * NT;
        sact[r] = idx < SDL;
        int i2 = sact[r] ? idx : 0;
        int pz_ = i2 / (PH * PWD);
        int rem = i2 - pz_ * (PH * PWD);
        int py_ = rem / PWD;
        int px_ = rem - py_ * PWD;
        int gz = bz + pz_ - 1, gy = by + py_ - 1, gx = bx + px_ - 1;
        bool v = (gz >= 0 && gz < Dz && gy >= 0 && gy < Hy && gx >= 0 && gx < Wx);
        svld[r] = v;
        soff[r] = v ? (gz * Hy + gy) * Wx + gx : 0;
        sdst[r] = i2;
    }

    // weights pre-packed: entry (ogw, cl, kzky, half): half0 -> (w1,w0), half1 -> (w3,w2)
    auto stage_w = [&](int chunk) {
        ull* wd = wsmU[chunk & 1];
        for (int i = tid; i < WPC; i += NT) {
            int ogw = i / (CC * 32);
            int r = i - ogw * (CC * 32);
            int cl = r >> 5;
            int e = r & 31;
            int kzky = e >> 1;
            int half = e & 1;
            const float* wk = wt +
                (((size_t)(chunk * CC + cl)) * Cout + (blockIdx.y * OG + ogw)) * 64 +
                kzky * 4;
            float lo, hi;
            if (half == 0) { lo = wk[1]; hi = wk[0]; }
            else           { lo = wk[3]; hi = wk[2]; }
            wd[i] = pack2f(lo, hi);
        }
    };

    ull acc[2][2][4];  // [cy][cx][pz*2+py] = (px0, px1)
#pragma unroll
    for (int cy = 0; cy < 2; cy++)
#pragma unroll
        for (int cx = 0; cx < 2; cx++)
#pragma unroll
            for (int p = 0; p < 4; p++) acc[cy][cx][p] = 0ull;

    // initial staging
    stage_w(0);
    {
        float* vb = vsm[0];
        const float* pc = inb;
#pragma unroll
        for (int r = 0; r < RMAX; r++) {
            if (sact[r]) vb[sdst[r]] = svld[r] ? pc[soff[r]] : 0.f;
        }
    }
    __syncthreads();

    const int tbase = (tzi * PH + 2 * tyi) * PWD + 2 * txi;
    const int DDt[2][2] = {{0, -1}, {1, 0}};
    const int KKt[2][2] = {{1, 3}, {0, 2}};

    for (int c = 0; c < Cin; c++) {
        if ((c & (CC - 1)) == 0 && c + CC < Cin) stage_w(c / CC + 1);

        // prefetch next channel into registers (loads in flight during compute)
        float pref[RMAX];
        const bool havenext = (c + 1 < Cin);
        if (havenext) {
            const float* pc = inb + (size_t)(c + 1) * S;
#pragma unroll
            for (int r = 0; r < RMAX; r++) {
                pref[r] = (sact[r] && svld[r]) ? pc[soff[r]] : 0.f;
            }
        }

        const float* vb = vsm[c & 1];
        const ull* wcU = wsmU[(c / CC) & 1] + ((size_t)og * CC + (c & (CC - 1))) * 32;

#pragma unroll
        for (int jz = 0; jz < 3; jz++) {
            ull vp[4][3];
#pragma unroll
            for (int ry = 0; ry < 4; ry++) {
                float x0 = vb[tbase + (jz * PH + ry) * PWD + 0];
                float x1 = vb[tbase + (jz * PH + ry) * PWD + 1];
                float x2 = vb[tbase + (jz * PH + ry) * PWD + 2];
                float x3 = vb[tbase + (jz * PH + ry) * PWD + 3];
                vp[ry][0] = pack2f(x0, x1);
                vp[ry][1] = pack2f(x1, x2);
                vp[ry][2] = pack2f(x2, x3);
            }
#pragma unroll
            for (int pz = 0; pz < 2; pz++)
#pragma unroll
                for (int sz = 0; sz < 2; sz++) {
                    if (1 + DDt[pz][sz] != jz) continue;  // compile-time pruned
                    const int kz = KKt[pz][sz];
#pragma unroll
                    for (int py = 0; py < 2; py++)
#pragma unroll
                        for (int sy = 0; sy < 2; sy++) {
                            const int jy0 = 1 + DDt[py][sy];
                            const int ky = KKt[py][sy];
                            const ull wa = wcU[(kz * 4 + ky) * 2 + 0];  // (w1,w0)
                            const ull wb = wcU[(kz * 4 + ky) * 2 + 1];  // (w3,w2)
#pragma unroll
                            for (int cy = 0; cy < 2; cy++) {
                                const int row = jy0 + cy;
#pragma unroll
                                for (int cx = 0; cx < 2; cx++) {
                                    fma2(acc[cy][cx][pz * 2 + py], vp[row][cx + 1], wa);
                                    fma2(acc[cy][cx][pz * 2 + py], vp[row][cx], wb);
                                }
                            }
                        }
                }
        }

        // write prefetched channel into the other buffer
        if (havenext) {
            float* vb1 = vsm[(c + 1) & 1];
#pragma unroll
            for (int r = 0; r < RMAX; r++) {
                if (sact[r]) vb1[sdst[r]] = pref[r];
            }
        }
        __syncthreads();
    }

    // ---------------- epilogue (scalar stores) ----------------
    const int mz = bz + tzi;
    if (mz >= Dz) return;
    const float bv = bias[o];
    const int Ho = 2 * Hy, Wo = 2 * Wx;
    float* ob = out + ((size_t)b * Cout + o) * (size_t)(2 * Dz) * Ho * Wo;
    const int my0 = by + 2 * tyi;
    const int mx0 = bx + 2 * txi;

#pragma unroll
    for (int cy = 0; cy < 2; cy++) {
        int my = my0 + cy;
        if (my >= Hy) continue;
#pragma unroll
        for (int cx = 0; cx < 2; cx++) {
            int mx = mx0 + cx;
            if (mx >= Wx) continue;
#pragma unroll
            for (int pz = 0; pz < 2; pz++)
#pragma unroll
                for (int py = 0; py < 2; py++) {
                    float2 a = unpk2(acc[cy][cx][pz * 2 + py]);
                    float r0 = a.x + bv;
                    float r1 = a.y + bv;
                    if (SIG) {
                        r0 = 1.f / (1.f + __expf(-r0));
                        r1 = 1.f / (1.f + __expf(-r1));
                    }
                    size_t base = (size_t)(2 * mz + pz) * Ho * Wo +
                                  (size_t)(2 * my + py) * Wo + (size_t)(2 * mx);
                    ob[base] = r0;
                    ob[base + 1] = r1;
                }
        }
    }
}

// ---------------- host-side helpers ----------------
static void run_bn(float* t, int C, int S, const float* g, const float* be,
                   float* part, float* scale, float* shift) {
    dim3 gp(C, BN_NB);
    bn_partial<<<gp, 256>>>(t, C, S, part);
    bn_finalize<<<(C + 127) / 128, 128>>>(part, C, (float)(BATCH * S), g, be, scale, shift);
    size_t total = (size_t)BATCH * C * S;
    bn_apply_relu<<<(unsigned)((total + 255) / 256), 256>>>(t, C, S, scale, shift);
}

template <int TILEY, int TILEX, int OG, int CC, bool SIG>
static void run_convt5(const float* in, const float* wt, const float* bias,
                       float* out, int Cin, int Cout, int Dz, int Hy, int Wx) {
    int ntx = (Wx + TILEX - 1) / TILEX;
    int nty = (Hy + TILEY - 1) / TILEY;
    int ntz = (Dz + 3) / 4;
    dim3 grid(ntx * nty * ntz, Cout / OG, BATCH);
    convt5_kernel<TILEY, TILEX, OG, CC, SIG>
        <<<grid, TILEY * TILEX * OG>>>(in, wt, bias, out, Cin, Cout, Dz, Hy, Wx, ntx, nty);
}

extern "C" void kernel_launch(void* const* d_in, const int* in_sizes, int n_in,
                              void* d_out, int out_size) {
    const float* x_in = (const float*)d_in[0];
    const float* y_in = (const float*)d_in[1];
    const float* tables = (const float*)d_in[2];
    const float* g0 = (const float*)d_in[3];
    const float* be0 = (const float*)d_in[4];
    const float* g1 = (const float*)d_in[5];
    const float* be1 = (const float*)d_in[6];
    const float* g2 = (const float*)d_in[7];
    const float* be2 = (const float*)d_in[8];
    const float* g3 = (const float*)d_in[9];
    const float* be3 = (const float*)d_in[10];
    const float* g4 = (const float*)d_in[11];
    const float* be4 = (const float*)d_in[12];
    const float* w1 = (const float*)d_in[13];
    const float* b1 = (const float*)d_in[14];
    const float* w2 = (const float*)d_in[15];
    const float* b2 = (const float*)d_in[16];
    const float* w3 = (const float*)d_in[17];
    const float* b3 = (const float*)d_in[18];
    const float* w4 = (const float*)d_in[19];
    const float* b4 = (const float*)d_in[20];
    const float* w5 = (const float*)d_in[21];
    const float* b5 = (const float*)d_in[22];

    float *wproj, *t0, *t1, *t2, *t3, *t4, *part, *scale, *shift;
    cudaGetSymbolAddress((void**)&wproj, g_wproj);
    cudaGetSymbolAddress((void**)&t0, g_t0);
    cudaGetSymbolAddress((void**)&t1, g_t1);
    cudaGetSymbolAddress((void**)&t2, g_t2);
    cudaGetSymbolAddress((void**)&t3, g_t3);
    cudaGetSymbolAddress((void**)&t4, g_t4);
    cudaGetSymbolAddress((void**)&part, g_part);
    cudaGetSymbolAddress((void**)&scale, g_scale);
    cudaGetSymbolAddress((void**)&shift, g_shift);

    // 1) hypernet weights
    {
        int tot = NHEADS * CPROJ * CIN0;
        hyper_kernel<<<(tot + 255) / 256, 256>>>(y_in, tables, wproj);
    }
    // 2) dynamic 1x1x1 projection -> t0 [2,1024,4,6,8]
    {
        dim3 pg(128, BATCH);
        proj_kernel2<<<pg, 192>>>(x_in, wproj, t0);
    }
    // 3) decoder stack
    run_bn(t0, 1024, 4 * 6 * 8, g0, be0, part, scale, shift);
    run_convt5<6, 8, 2, 16, false>(t0, w1, b1, t1, 1024, 512, 4, 6, 8);
    run_bn(t1, 512, 8 * 12 * 16, g1, be1, part, scale, shift);
    run_convt5<12, 16, 1, 32, false>(t1, w2, b2, t2, 512, 256, 8, 12, 16);
    run_bn(t2, 256, 16 * 24 * 32, g2, be2, part, scale, shift);
    run_convt5<12, 16, 1, 32, false>(t2, w3, b3, t3, 256, 128, 16, 24, 32);
    run_bn(t3, 128, 32 * 48 * 64, g3, be3, part, scale, shift);
    run_convt5<12, 16, 1, 32, false>(t3, w4, b4, t4, 128, 32, 32, 48, 64);
    run_bn(t4, 32, 64 * 96 * 128, g4, be4, part, scale, shift);
    run_convt5<12, 16, 1, 32, true>(t4, w5, b5, (float*)d_out, 32, 1, 64, 96, 128);
}